// round 8
// baseline (speedup 1.0000x reference)
#include <cuda_runtime.h>
#include <cuda_fp16.h>
#include <cstdint>

// LinearSelfAttention via fp16-in/fp32-acc mma.sync (m16n8k16), all-NT GEMMs.
// out = H + ((P G Q - u v^T) H) / n,  G = H H^T, u = P h_n, v = Q^T h_n.
// Chain (NT: C[m,n] = sum_k A[m,k] B[n,k]):
//   G  = Hp (x) Hp       symmetric: 6 upper tiles + mirror, full K, fp16 out
//   T' = Qt (x) G        ( = (G Q)^T )      [full-K smem prefetch]
//   W  = Pp (x) T' - u v^T                  [full-K smem prefetch]
//   out= H + (W (x) Ht)/n                   [depth-4 pipeline]

#define RDIM 257
#define NCOL 2049
#define NBAT 16
#define INV_N (1.0f / 2048.0f)

#define MP   384
#define KHP  2176
#define LDS_ 384
#define GB_  ((size_t)MP * LDS_)
#define HTB  ((size_t)KHP * MP)
#define HB   ((size_t)RDIM * NCOL)

__device__ __half g_Hp[NBAT][MP * KHP];
__device__ __half g_Ht[NBAT][KHP * MP];
__device__ __half g_Pp[MP * LDS_];
__device__ __half g_Qt[MP * LDS_];
__device__ __half g_G[NBAT][MP * LDS_];
__device__ __half g_Tt[NBAT][MP * LDS_];
__device__ __half g_W[NBAT][MP * LDS_];
__device__ float  g_u[NBAT][MP];   // pads stay 0
__device__ float  g_v[NBAT][MP];

// ---------------------------------------------------------------------------
__device__ __forceinline__ uint32_t smem_u32(const void* p) {
    uint32_t a;
    asm("{ .reg .u64 t; cvta.to.shared.u64 t, %1; cvt.u32.u64 %0, t; }"
        : "=r"(a) : "l"(p));
    return a;
}
__device__ __forceinline__ void cp16(void* s, const void* g) {
    uint32_t sa = smem_u32(s);
    asm volatile("cp.async.cg.shared.global [%0], [%1], 16;"
                 :: "r"(sa), "l"(g) : "memory");
}
#define CP_COMMIT() asm volatile("cp.async.commit_group;" ::: "memory")
#define CP_WAITN(n) asm volatile("cp.async.wait_group %0;" :: "n"(n) : "memory")

__device__ __forceinline__ void mma16(float* c, const uint32_t* a,
                                      const uint32_t* b) {
    asm volatile(
        "mma.sync.aligned.m16n8k16.row.col.f32.f16.f16.f32 "
        "{%0,%1,%2,%3}, {%4,%5,%6,%7}, {%8,%9}, {%0,%1,%2,%3};"
        : "+f"(c[0]), "+f"(c[1]), "+f"(c[2]), "+f"(c[3])
        : "r"(a[0]), "r"(a[1]), "r"(a[2]), "r"(a[3]), "r"(b[0]), "r"(b[1]));
}

// ---------------------------------------------------------------------------
// Stage 1: G = Hp (x) Hp, symmetric (6 upper tiles), full K=2176, depth-3.
// grid (6,1,16), 256 thr, smem 6*128*72*2 = 110592 B, 1 CTA/SM.
// ---------------------------------------------------------------------------
#define ABUF64 (128 * 72)
#define SMEM_SYRK (6 * ABUF64 * 2)
#define NCH64 34   // 2176 / 64

__device__ __forceinline__ void load64(__half* dst, const __half* __restrict__ g,
                                       int ld, int r0, int k0, int tid) {
    const __half* gp = g + (size_t)r0 * ld + k0;
    const int kk = (tid & 7) * 8;
    const int r = tid >> 3;
#pragma unroll
    for (int i = 0; i < 4; i++)
        cp16(dst + (r + i * 32) * 72 + kk, gp + (size_t)(r + i * 32) * ld + kk);
}

__global__ void __launch_bounds__(256) k_syrk() {
    extern __shared__ __half sm[];
    __half* As = sm;
    __half* Bs = sm + 3 * ABUF64;

    const int tid = threadIdx.x;
    const int b = blockIdx.z;
    const int TI[6] = {0, 0, 0, 1, 1, 2};
    const int TJ[6] = {0, 1, 2, 1, 2, 2};
    const int ti = TI[blockIdx.x], tj = TJ[blockIdx.x];
    const int m0 = ti * 128, n0 = tj * 128;

    const __half* Hb = g_Hp[b];
    __half* Gb = g_G[b];

    const int lane = tid & 31, wid = tid >> 5;
    const int wm = (wid & 3) * 32;
    const int wn = (wid >> 2) * 64;
    const int g = lane >> 2, tg = lane & 3;

    float acc[2][8][4];
#pragma unroll
    for (int i = 0; i < 2; i++)
#pragma unroll
        for (int j = 0; j < 8; j++)
#pragma unroll
            for (int r = 0; r < 4; r++) acc[i][j][r] = 0.0f;

    // prologue: chunks 0,1
    load64(As, Hb, KHP, m0, 0, tid);
    load64(Bs, Hb, KHP, n0, 0, tid);
    CP_COMMIT();
    load64(As + ABUF64, Hb, KHP, m0, 64, tid);
    load64(Bs + ABUF64, Hb, KHP, n0, 64, tid);
    CP_COMMIT();

    for (int c = 0; c < NCH64; c++) {
        if (c + 2 < NCH64) {
            const int nb = (c + 2) % 3;
            const int k0 = (c + 2) * 64;
            load64(As + nb * ABUF64, Hb, KHP, m0, k0, tid);
            load64(Bs + nb * ABUF64, Hb, KHP, n0, k0, tid);
        }
        CP_COMMIT();
        CP_WAITN(2);
        __syncthreads();

        const __half* As_ = As + (c % 3) * ABUF64;
        const __half* Bs_ = Bs + (c % 3) * ABUF64;
#pragma unroll
        for (int ks = 0; ks < 4; ks++) {
            const int k = ks * 16;
            uint32_t a[2][4], bf[8][2];
#pragma unroll
            for (int mt = 0; mt < 2; mt++) {
                const int r = wm + mt * 16 + g;
                a[mt][0] = *(const uint32_t*)&As_[r * 72 + k + 2 * tg];
                a[mt][1] = *(const uint32_t*)&As_[(r + 8) * 72 + k + 2 * tg];
                a[mt][2] = *(const uint32_t*)&As_[r * 72 + k + 2 * tg + 8];
                a[mt][3] = *(const uint32_t*)&As_[(r + 8) * 72 + k + 2 * tg + 8];
            }
#pragma unroll
            for (int nt = 0; nt < 8; nt++) {
                const int cn = wn + nt * 8 + g;
                bf[nt][0] = *(const uint32_t*)&Bs_[cn * 72 + k + 2 * tg];
                bf[nt][1] = *(const uint32_t*)&Bs_[cn * 72 + k + 2 * tg + 8];
            }
#pragma unroll
            for (int mt = 0; mt < 2; mt++)
#pragma unroll
                for (int nt = 0; nt < 8; nt++) mma16(acc[mt][nt], a[mt], bf[nt]);
        }
        __syncthreads();
    }

    // epilogue: fp16 own tile + mirror for off-diagonal
#pragma unroll
    for (int mt = 0; mt < 2; mt++) {
#pragma unroll
        for (int half = 0; half < 2; half++) {
            const int row = m0 + wm + mt * 16 + g + half * 8;
#pragma unroll
            for (int nt = 0; nt < 8; nt++) {
                const int col = n0 + wn + nt * 8 + tg * 2;
                const float v0 = acc[mt][nt][half * 2 + 0];
                const float v1 = acc[mt][nt][half * 2 + 1];
                *(__half2*)&Gb[(size_t)row * LDS_ + col] =
                    __floats2half2_rn(v0, v1);
                if (ti != tj) {
                    Gb[(size_t)col * LDS_ + row] = __float2half_rn(v0);
                    Gb[(size_t)(col + 1) * LDS_ + row] = __float2half_rn(v1);
                }
            }
        }
    }
}

// ---------------------------------------------------------------------------
// Small-K stages, K=288 (9 chunks of 32), FULL smem prefetch (no reuse).
//  MODE 1: T' = Qt (x) G          -> fp16
//  MODE 2: W  = Pp (x) T' - uv^T  -> fp16
// grid (3,3,16), 256 thr, smem 2*9*128*40*2 = 184320 B, 1 CTA/SM.
// ---------------------------------------------------------------------------
#define ABUF32 (128 * 40)
#define SMEM_FULL (18 * ABUF32 * 2)

__device__ __forceinline__ void load32(__half* dst, const __half* __restrict__ g,
                                       int ld, int r0, int k0, int tid) {
    const __half* gp = g + (size_t)r0 * ld + k0;
    const int kk = (tid & 3) * 8;
    const int r = tid >> 2;
    cp16(dst + r * 40 + kk, gp + (size_t)r * ld + kk);
    cp16(dst + (r + 64) * 40 + kk, gp + (size_t)(r + 64) * ld + kk);
}

template <int MODE>
__global__ void __launch_bounds__(256)
k_full(const __half* __restrict__ A, size_t sA,
       const __half* __restrict__ B, size_t sB,
       __half* __restrict__ C, size_t sC) {
    extern __shared__ __half sm[];
    __half* As = sm;                // 9 chunk buffers
    __half* Bs = sm + 9 * ABUF32;   // 9 chunk buffers

    const int tid = threadIdx.x;
    const int b = blockIdx.z;
    const int m0 = blockIdx.y * 128, n0 = blockIdx.x * 128;
    const __half* Ab = A + (size_t)b * sA;
    const __half* Bb = B + (size_t)b * sB;
    __half* Cb = C + (size_t)b * sC;

    const int lane = tid & 31, wid = tid >> 5;
    const int wm = (wid & 3) * 32;
    const int wn = (wid >> 2) * 64;
    const int g = lane >> 2, tg = lane & 3;

    // issue ALL loads up front (9 groups)
#pragma unroll
    for (int c = 0; c < 9; c++) {
        load32(As + c * ABUF32, Ab, LDS_, m0, c * 32, tid);
        load32(Bs + c * ABUF32, Bb, LDS_, n0, c * 32, tid);
        CP_COMMIT();
    }

    float acc[2][8][4];
#pragma unroll
    for (int i = 0; i < 2; i++)
#pragma unroll
        for (int j = 0; j < 8; j++)
#pragma unroll
            for (int r = 0; r < 4; r++) acc[i][j][r] = 0.0f;

#pragma unroll
    for (int c = 0; c < 9; c++) {
        switch (c) {  // wait until chunk c's group has landed
            case 0: CP_WAITN(8); break;
            case 1: CP_WAITN(7); break;
            case 2: CP_WAITN(6); break;
            case 3: CP_WAITN(5); break;
            case 4: CP_WAITN(4); break;
            case 5: CP_WAITN(3); break;
            case 6: CP_WAITN(2); break;
            case 7: CP_WAITN(1); break;
            default: CP_WAITN(0); break;
        }
        __syncthreads();

        const __half* As_ = As + c * ABUF32;
        const __half* Bs_ = Bs + c * ABUF32;
#pragma unroll
        for (int ks = 0; ks < 2; ks++) {
            const int k = ks * 16;
            uint32_t a[2][4], bf[8][2];
#pragma unroll
            for (int mt = 0; mt < 2; mt++) {
                const int r = wm + mt * 16 + g;
                a[mt][0] = *(const uint32_t*)&As_[r * 40 + k + 2 * tg];
                a[mt][1] = *(const uint32_t*)&As_[(r + 8) * 40 + k + 2 * tg];
                a[mt][2] = *(const uint32_t*)&As_[r * 40 + k + 2 * tg + 8];
                a[mt][3] = *(const uint32_t*)&As_[(r + 8) * 40 + k + 2 * tg + 8];
            }
#pragma unroll
            for (int nt = 0; nt < 8; nt++) {
                const int cn = wn + nt * 8 + g;
                bf[nt][0] = *(const uint32_t*)&Bs_[cn * 40 + k + 2 * tg];
                bf[nt][1] = *(const uint32_t*)&Bs_[cn * 40 + k + 2 * tg + 8];
            }
#pragma unroll
            for (int mt = 0; mt < 2; mt++)
#pragma unroll
                for (int nt = 0; nt < 8; nt++) mma16(acc[mt][nt], a[mt], bf[nt]);
        }
    }

    // epilogue -> fp16
#pragma unroll
    for (int mt = 0; mt < 2; mt++) {
#pragma unroll
        for (int half = 0; half < 2; half++) {
            const int row = m0 + wm + mt * 16 + g + half * 8;
            float uu = 0.0f;
            if (MODE == 2) uu = g_u[b][row];
#pragma unroll
            for (int nt = 0; nt < 8; nt++) {
                const int col = n0 + wn + nt * 8 + tg * 2;
                float v0 = acc[mt][nt][half * 2 + 0];
                float v1 = acc[mt][nt][half * 2 + 1];
                if (MODE == 2) {
                    v0 -= uu * g_v[b][col];
                    v1 -= uu * g_v[b][col + 1];
                }
                *(__half2*)&Cb[(size_t)row * LDS_ + col] =
                    __floats2half2_rn(v0, v1);
            }
        }
    }
}

// ---------------------------------------------------------------------------
// Stage 6: out = H + (W (x) Ht)/n. K=288, depth-4 pipeline, 2 CTAs/SM.
// grid (17,3,16), smem 8*128*40*2 = 81920 B.
// ---------------------------------------------------------------------------
#define SMEM_OUT (8 * ABUF32 * 2)

__global__ void __launch_bounds__(256, 2)
k_out(const float* __restrict__ H, float* __restrict__ out) {
    extern __shared__ __half sm[];
    __half* As = sm;                // 4 buffers
    __half* Bs = sm + 4 * ABUF32;   // 4 buffers

    const int tid = threadIdx.x;
    const int b = blockIdx.z;
    const int m0 = blockIdx.y * 128, n0 = blockIdx.x * 128;
    const __half* Ab = g_W[b];
    const __half* Bb = g_Ht[b];
    const float* Hb = H + (size_t)b * HB;
    float* Ob = out + (size_t)b * HB;

    const int lane = tid & 31, wid = tid >> 5;
    const int wm = (wid & 3) * 32;
    const int wn = (wid >> 2) * 64;
    const int g = lane >> 2, tg = lane & 3;

    float acc[2][8][4];
#pragma unroll
    for (int i = 0; i < 2; i++)
#pragma unroll
        for (int j = 0; j < 8; j++)
#pragma unroll
            for (int r = 0; r < 4; r++) acc[i][j][r] = 0.0f;

    // prologue: chunks 0,1,2
#pragma unroll
    for (int c = 0; c < 3; c++) {
        load32(As + c * ABUF32, Ab, LDS_, m0, c * 32, tid);
        load32(Bs + c * ABUF32, Bb, MP, n0, c * 32, tid);
        CP_COMMIT();
    }

    for (int c = 0; c < 9; c++) {
        if (c + 3 < 9) {
            const int nb = (c + 3) & 3;
            const int k0 = (c + 3) * 32;
            load32(As + nb * ABUF32, Ab, LDS_, m0, k0, tid);
            load32(Bs + nb * ABUF32, Bb, MP, n0, k0, tid);
        }
        CP_COMMIT();
        CP_WAITN(3);
        __syncthreads();

        const __half* As_ = As + (c & 3) * ABUF32;
        const __half* Bs_ = Bs + (c & 3) * ABUF32;
#pragma unroll
        for (int ks = 0; ks < 2; ks++) {
            const int k = ks * 16;
            uint32_t a[2][4], bf[8][2];
#pragma unroll
            for (int mt = 0; mt < 2; mt++) {
                const int r = wm + mt * 16 + g;
                a[mt][0] = *(const uint32_t*)&As_[r * 40 + k + 2 * tg];
                a[mt][1] = *(const uint32_t*)&As_[(r + 8) * 40 + k + 2 * tg];
                a[mt][2] = *(const uint32_t*)&As_[r * 40 + k + 2 * tg + 8];
                a[mt][3] = *(const uint32_t*)&As_[(r + 8) * 40 + k + 2 * tg + 8];
            }
#pragma unroll
            for (int nt = 0; nt < 8; nt++) {
                const int cn = wn + nt * 8 + g;
                bf[nt][0] = *(const uint32_t*)&Bs_[cn * 40 + k + 2 * tg];
                bf[nt][1] = *(const uint32_t*)&Bs_[cn * 40 + k + 2 * tg + 8];
            }
#pragma unroll
            for (int mt = 0; mt < 2; mt++)
#pragma unroll
                for (int nt = 0; nt < 8; nt++) mma16(acc[mt][nt], a[mt], bf[nt]);
        }
        __syncthreads();
    }

    // epilogue: out = H + acc/n, guarded
#pragma unroll
    for (int mt = 0; mt < 2; mt++) {
#pragma unroll
        for (int half = 0; half < 2; half++) {
            const int row = m0 + wm + mt * 16 + g + half * 8;
            if (row >= RDIM) continue;
#pragma unroll
            for (int nt = 0; nt < 8; nt++) {
                const int col = n0 + wn + nt * 8 + tg * 2;
                const float v0 = acc[mt][nt][half * 2 + 0];
                const float v1 = acc[mt][nt][half * 2 + 1];
                const size_t idx = (size_t)row * NCOL + col;
                if (col < NCOL) Ob[idx] = Hb[idx] + v0 * INV_N;
                if (col + 1 < NCOL) Ob[idx + 1] = Hb[idx + 1] + v1 * INV_N;
            }
        }
    }
}

// ---------------------------------------------------------------------------
// fused setup: z<16 padH(batch z); z==16 padPQ; z==17 uv.
// grid (34, 12, 18), block 256.
// ---------------------------------------------------------------------------
__global__ void k_setup(const float* __restrict__ H, const float* __restrict__ P,
                        const float* __restrict__ Q) {
    __shared__ float t[32][65];
    const int tid = threadIdx.x;
    const int z = blockIdx.z;

    if (z < NBAT) {
        const int b = z;
        const int c0 = blockIdx.x * 64;
        const int r0 = blockIdx.y * 32;
        const float* Hb = H + (size_t)b * HB;
        const int tx = tid & 31, ty = tid >> 5;
#pragma unroll
        for (int i = 0; i < 4; i++) {
            const int r = r0 + ty + i * 8;
            const int c = c0 + 2 * tx;
            float v0 = 0.0f, v1 = 0.0f;
            if (r < RDIM) {
                if (c < NCOL) v0 = Hb[(size_t)r * NCOL + c];
                if (c + 1 < NCOL) v1 = Hb[(size_t)r * NCOL + c + 1];
            }
            t[ty + i * 8][2 * tx] = v0;
            t[ty + i * 8][2 * tx + 1] = v1;
            *(__half2*)&g_Hp[b][(size_t)r * KHP + c] = __floats2half2_rn(v0, v1);
        }
        __syncthreads();
#pragma unroll
        for (int i = 0; i < 4; i++) {
            const int cl = tid >> 2;
            const int pr = (tid & 3) + 4 * i;
            const float v0 = t[2 * pr][cl];
            const float v1 = t[2 * pr + 1][cl];
            *(__half2*)&g_Ht[b][(size_t)(c0 + cl) * MP + r0 + 2 * pr] =
                __floats2half2_rn(v0, v1);
        }
    } else if (z == NBAT) {
        if (blockIdx.x >= 12) return;
        const int c0 = blockIdx.x * 32, r0 = blockIdx.y * 32;
        const int tx = tid & 31, ty = tid >> 5;
#pragma unroll
        for (int i = 0; i < 4; i++) {
            const int r = r0 + ty + i * 8, c = c0 + tx;
            const bool in = (r < RDIM && c < RDIM);
            g_Pp[(size_t)r * LDS_ + c] =
                __float2half_rn(in ? P[(size_t)r * RDIM + c] : 0.0f);
            t[ty + i * 8][tx] = in ? Q[(size_t)r * RDIM + c] : 0.0f;
        }
        __syncthreads();
#pragma unroll
        for (int i = 0; i < 4; i++) {
            const int c = c0 + ty + i * 8, r = r0 + tx;
            g_Qt[(size_t)c * LDS_ + r] = __float2half_rn(t[tx][ty + i * 8]);
        }
    } else {
        if (blockIdx.x >= NBAT || blockIdx.y != 0) return;
        const int b = blockIdx.x;
        const float* Hb = H + (size_t)b * HB;
        __shared__ float hn[RDIM];
        for (int e = tid; e < RDIM; e += 256)
            hn[e] = Hb[(size_t)e * NCOL + (NCOL - 1)];
        __syncthreads();
        for (int i = tid; i < RDIM; i += 256) {
            float su = 0.0f, sv = 0.0f;
            for (int e = 0; e < RDIM; e++) {
                su += P[(size_t)i * RDIM + e] * hn[e];
                sv += hn[e] * Q[(size_t)e * RDIM + i];
            }
            g_u[b][i] = su;
            g_v[b][i] = sv;
        }
    }
}

// ---------------------------------------------------------------------------
extern "C" void kernel_launch(void* const* d_in, const int* in_sizes, int n_in,
                              void* d_out, int out_size) {
    const float* H = (const float*)d_in[0];
    const float* P = (const float*)d_in[1];
    const float* Q = (const float*)d_in[2];
    float* out = (float*)d_out;

    cudaFuncSetAttribute(k_syrk, cudaFuncAttributeMaxDynamicSharedMemorySize,
                         SMEM_SYRK);
    cudaFuncSetAttribute(k_full<1>,
                         cudaFuncAttributeMaxDynamicSharedMemorySize, SMEM_FULL);
    cudaFuncSetAttribute(k_full<2>,
                         cudaFuncAttributeMaxDynamicSharedMemorySize, SMEM_FULL);
    cudaFuncSetAttribute(k_out, cudaFuncAttributeMaxDynamicSharedMemorySize,
                         SMEM_OUT);

    __half *Pp, *Qt, *Gm, *Tm, *Wm;
    cudaGetSymbolAddress((void**)&Pp, g_Pp);
    cudaGetSymbolAddress((void**)&Qt, g_Qt);
    cudaGetSymbolAddress((void**)&Gm, g_G);
    cudaGetSymbolAddress((void**)&Tm, g_Tt);
    cudaGetSymbolAddress((void**)&Wm, g_W);

    // 1) setup: pad H -> Hp/Ht, pad P/Q^T, compute u/v
    k_setup<<<dim3(34, 12, NBAT + 2), 256>>>(H, P, Q);
    // 2) G = Hp (x) Hp (symmetric, full K, fp16 out)
    k_syrk<<<dim3(6, 1, NBAT), 256, SMEM_SYRK>>>();
    // 3) T' = Qt (x) G
    k_full<1><<<dim3(3, 3, NBAT), 256, SMEM_FULL>>>(Qt, 0, Gm, GB_, Tm, GB_);
    // 4) W = Pp (x) T' - u v^T
    k_full<2><<<dim3(3, 3, NBAT), 256, SMEM_FULL>>>(Pp, 0, Tm, GB_, Wm, GB_);
    // 5) out = H + (W (x) Ht)/n
    k_out<<<dim3(17, 3, NBAT), 256, SMEM_OUT>>>(H, out);
}

// round 9
// speedup vs baseline: 1.1313x; 1.1313x over previous
#include <cuda_runtime.h>
#include <cuda_fp16.h>
#include <cstdint>

// LinearSelfAttention via fp16-in/fp32-acc mma.sync (m16n8k16) + ldmatrix.
// out = H + ((P G Q - u v^T) H) / n,  G = H H^T, u = P h_n, v = Q^T h_n.
// Chain (all NT: C[m,n] = sum_k A[m,k] B[n,k]):
//   G  = Hp (x) Hp    symmetric 6 tiles + mirror, split-K x3, fp32 partials
//   T' = Qt (x) G     ( = (G Q)^T )
//   W  = Pp (x) T' - u v^T
//   out= H + (W (x) Ht)/n
// All GEMM smem tiles: 128 rows x 64 halfs (128 B), XOR swizzle (c ^ (r&7)),
// fragments loaded with ldmatrix.x4 (conflict-free).

#define RDIM 257
#define NCOL 2049
#define NBAT 16
#define INV_N (1.0f / 2048.0f)

#define MP   384
#define KHP  2176
#define LDS_ 384
#define GB_  ((size_t)MP * LDS_)
#define HB   ((size_t)RDIM * NCOL)

__device__ __half g_Hp[NBAT][MP * KHP];
__device__ __half g_Ht[NBAT][KHP * MP];
__device__ __half g_Pp[MP * LDS_];
__device__ __half g_Qt[MP * LDS_];
__device__ float  g_Gp[3][NBAT][MP * LDS_];   // split-K partials
__device__ __half g_G[NBAT][MP * LDS_];
__device__ __half g_Tt[NBAT][MP * LDS_];
__device__ __half g_W[NBAT][MP * LDS_];
__device__ float  g_u[NBAT][MP];   // pads stay 0
__device__ float  g_v[NBAT][MP];

// ---------------------------------------------------------------------------
__device__ __forceinline__ uint32_t smem_u32(const void* p) {
    uint32_t a;
    asm("{ .reg .u64 t; cvta.to.shared.u64 t, %1; cvt.u32.u64 %0, t; }"
        : "=r"(a) : "l"(p));
    return a;
}
__device__ __forceinline__ void cp16a(uint32_t sa, const void* g) {
    asm volatile("cp.async.cg.shared.global [%0], [%1], 16;"
                 :: "r"(sa), "l"(g) : "memory");
}
#define CP_COMMIT() asm volatile("cp.async.commit_group;" ::: "memory")
#define CP_WAITN(n) asm volatile("cp.async.wait_group %0;" :: "n"(n) : "memory")

__device__ __forceinline__ void mma8(float* c, const uint32_t* a,
                                     const uint32_t* b) {
    asm volatile(
        "mma.sync.aligned.m16n8k16.row.col.f32.f16.f16.f32 "
        "{%0,%1,%2,%3}, {%4,%5,%6,%7}, {%8,%9}, {%0,%1,%2,%3};"
        : "+f"(c[0]), "+f"(c[1]), "+f"(c[2]), "+f"(c[3])
        : "r"(a[0]), "r"(a[1]), "r"(a[2]), "r"(a[3]), "r"(b[0]), "r"(b[1]));
}
__device__ __forceinline__ void ldsm4(uint32_t* r, uint32_t a) {
    asm volatile(
        "ldmatrix.sync.aligned.m8n8.x4.shared.b16 {%0,%1,%2,%3}, [%4];"
        : "=r"(r[0]), "=r"(r[1]), "=r"(r[2]), "=r"(r[3]) : "r"(a));
}

// ---------------------------------------------------------------------------
// Swizzled tile load: 128 rows x 64 halfs (128 B/row), chunk c at (c^(r&7)).
// ---------------------------------------------------------------------------
#define TILE_B 16384   // bytes per tile buffer

__device__ __forceinline__ void loadS(uint32_t sbase, const __half* __restrict__ g,
                                      int ld, int r0, int k0, int tid) {
    const int chunk = tid & 7;
    const int rb = tid >> 3;
    const __half* gp = g + (size_t)r0 * ld + k0 + chunk * 8;
#pragma unroll
    for (int i = 0; i < 4; i++) {
        const int r = rb + i * 32;
        const uint32_t off = (uint32_t)(r * 128 + ((chunk ^ (r & 7)) << 4));
        cp16a(sbase + off, gp + (size_t)r * ld);
    }
}

// One BK=64 chunk of MMAs from swizzled tiles via ldmatrix.
__device__ __forceinline__ void chunk_mma(uint32_t Ab, uint32_t Bb, int lane,
                                          int wm, int wn, float (&acc)[2][8][4]) {
    const int rA = lane & 15;
    const int hi = lane >> 4;
#pragma unroll
    for (int ks = 0; ks < 4; ks++) {
        uint32_t a[2][4], bt[4][4];
#pragma unroll
        for (int mt = 0; mt < 2; mt++) {
            const int row = wm + mt * 16 + rA;
            ldsm4(a[mt], Ab + row * 128 + (((ks * 2 + hi) ^ (row & 7)) << 4));
        }
#pragma unroll
        for (int n2 = 0; n2 < 4; n2++) {
            const int row = wn + n2 * 16 + rA;
            ldsm4(bt[n2], Bb + row * 128 + (((ks * 2 + hi) ^ (row & 7)) << 4));
        }
#pragma unroll
        for (int mt = 0; mt < 2; mt++)
#pragma unroll
            for (int n2 = 0; n2 < 4; n2++) {
                uint32_t b0[2] = {bt[n2][0], bt[n2][2]};
                uint32_t b1[2] = {bt[n2][1], bt[n2][3]};
                mma8(acc[mt][2 * n2 + 0], a[mt], b0);
                mma8(acc[mt][2 * n2 + 1], a[mt], b1);
            }
    }
}

// ---------------------------------------------------------------------------
// Stage 1: G partials = Hp (x) Hp, symmetric 6 tiles, split-K x3, depth-3.
// grid (6,1,48), 256 thr, smem 6*16KB = 98304 B, 2 CTAs/SM.
// ---------------------------------------------------------------------------
#define SMEM_GEMM (6 * TILE_B)

__global__ void __launch_bounds__(256, 2) k_syrk() {
    extern __shared__ __half sm[];
    const uint32_t sbase = smem_u32(sm);

    const int tid = threadIdx.x;
    const int b = blockIdx.z / 3;
    const int sp = blockIdx.z % 3;
    const int TI[6] = {0, 0, 0, 1, 1, 2};
    const int TJ[6] = {0, 1, 2, 1, 2, 2};
    const int ti = TI[blockIdx.x], tj = TJ[blockIdx.x];
    const int m0 = ti * 128, n0 = tj * 128;
    const int c0 = (sp == 0) ? 0 : (12 + (sp - 1) * 11);
    const int nc = (sp == 0) ? 12 : 11;

    const __half* Hb = g_Hp[b];
    float* Cf = &g_Gp[sp][b][0];

    const int lane = tid & 31, wid = tid >> 5;
    const int wm = (wid & 3) * 32;
    const int wn = (wid >> 2) * 64;
    const int g = lane >> 2, tg = lane & 3;

    float acc[2][8][4];
#pragma unroll
    for (int i = 0; i < 2; i++)
#pragma unroll
        for (int j = 0; j < 8; j++)
#pragma unroll
            for (int r = 0; r < 4; r++) acc[i][j][r] = 0.0f;

    // prologue: chunks 0,1
#pragma unroll
    for (int c = 0; c < 2; c++) {
        loadS(sbase + c * TILE_B, Hb, KHP, m0, (c0 + c) * 64, tid);
        loadS(sbase + (3 + c) * TILE_B, Hb, KHP, n0, (c0 + c) * 64, tid);
        CP_COMMIT();
    }

    for (int c = 0; c < nc; c++) {
        if (c + 2 < nc) {
            const int nb = (c + 2) % 3;
            const int k0 = (c0 + c + 2) * 64;
            loadS(sbase + nb * TILE_B, Hb, KHP, m0, k0, tid);
            loadS(sbase + (3 + nb) * TILE_B, Hb, KHP, n0, k0, tid);
        }
        CP_COMMIT();
        CP_WAITN(2);
        __syncthreads();
        chunk_mma(sbase + (c % 3) * TILE_B, sbase + (3 + c % 3) * TILE_B,
                  lane, wm, wn, acc);
        __syncthreads();
    }

    // epilogue: fp32 partial own tile + mirror for off-diagonal
#pragma unroll
    for (int mt = 0; mt < 2; mt++) {
#pragma unroll
        for (int half = 0; half < 2; half++) {
            const int row = m0 + wm + mt * 16 + g + half * 8;
#pragma unroll
            for (int nt = 0; nt < 8; nt++) {
                const int col = n0 + wn + nt * 8 + tg * 2;
                const float v0 = acc[mt][nt][half * 2 + 0];
                const float v1 = acc[mt][nt][half * 2 + 1];
                float2 st = {v0, v1};
                *(float2*)&Cf[(size_t)row * LDS_ + col] = st;
                if (ti != tj) {
                    Cf[(size_t)col * LDS_ + row] = v0;
                    Cf[(size_t)(col + 1) * LDS_ + row] = v1;
                }
            }
        }
    }
}

// ---------------------------------------------------------------------------
// reduce: G fp16 = p0 + p1 + p2
// ---------------------------------------------------------------------------
__global__ void k_reduce() {
    const size_t i = ((size_t)blockIdx.x * 256 + threadIdx.x) * 4;
    float4 x = *(const float4*)(&g_Gp[0][0][0] + i);
    float4 y = *(const float4*)(&g_Gp[1][0][0] + i);
    float4 z = *(const float4*)(&g_Gp[2][0][0] + i);
    __half* o = &g_G[0][0];
    *(__half2*)(o + i) = __floats2half2_rn(x.x + y.x + z.x, x.y + y.y + z.y);
    *(__half2*)(o + i + 2) = __floats2half2_rn(x.z + y.z + z.z, x.w + y.w + z.w);
}

// ---------------------------------------------------------------------------
// Generic small-K / out GEMM: K=320 (5 chunks of 64), depth-3, 2 CTAs/SM.
//  MODE 1: T' = Qt (x) G          -> fp16 (padded, unguarded)
//  MODE 2: W  = Pp (x) T' - uv^T  -> fp16 (padded, unguarded)
//  MODE 3: out= E + acc/n         -> fp32 (guarded, ldc=NCOL)
// ---------------------------------------------------------------------------
template <int MODE>
__global__ void __launch_bounds__(256, 2)
k_ld(const __half* __restrict__ A, size_t sA, int lda,
     const __half* __restrict__ B, size_t sB, int ldb,
     void* __restrict__ Cv, size_t sC, int ldc,
     const float* __restrict__ E) {
    extern __shared__ __half sm[];
    const uint32_t sbase = smem_u32(sm);

    const int tid = threadIdx.x;
    const int b = blockIdx.z;
    const int m0 = blockIdx.y * 128, n0 = blockIdx.x * 128;
    const __half* Ab = A + (size_t)b * sA;
    const __half* Bb = B + (size_t)b * sB;

    const int lane = tid & 31, wid = tid >> 5;
    const int wm = (wid & 3) * 32;
    const int wn = (wid >> 2) * 64;
    const int g = lane >> 2, tg = lane & 3;

    float acc[2][8][4];
#pragma unroll
    for (int i = 0; i < 2; i++)
#pragma unroll
        for (int j = 0; j < 8; j++)
#pragma unroll
            for (int r = 0; r < 4; r++) acc[i][j][r] = 0.0f;

#pragma unroll
    for (int c = 0; c < 2; c++) {
        loadS(sbase + c * TILE_B, Ab, lda, m0, c * 64, tid);
        loadS(sbase + (3 + c) * TILE_B, Bb, ldb, n0, c * 64, tid);
        CP_COMMIT();
    }

#pragma unroll
    for (int c = 0; c < 5; c++) {
        if (c + 2 < 5) {
            const int nb = (c + 2) % 3;
            loadS(sbase + nb * TILE_B, Ab, lda, m0, (c + 2) * 64, tid);
            loadS(sbase + (3 + nb) * TILE_B, Bb, ldb, n0, (c + 2) * 64, tid);
        }
        CP_COMMIT();
        CP_WAITN(2);
        __syncthreads();
        chunk_mma(sbase + (c % 3) * TILE_B, sbase + (3 + c % 3) * TILE_B,
                  lane, wm, wn, acc);
        __syncthreads();
    }

#pragma unroll
    for (int mt = 0; mt < 2; mt++) {
#pragma unroll
        for (int half = 0; half < 2; half++) {
            const int row = m0 + wm + mt * 16 + g + half * 8;
            if (MODE == 3 && row >= RDIM) continue;
            float uu = 0.0f;
            if (MODE == 2) uu = g_u[b][row];
#pragma unroll
            for (int nt = 0; nt < 8; nt++) {
                const int col = n0 + wn + nt * 8 + tg * 2;
                float v0 = acc[mt][nt][half * 2 + 0];
                float v1 = acc[mt][nt][half * 2 + 1];
                if (MODE == 1) {
                    __half* Ch = (__half*)Cv + (size_t)b * sC;
                    *(__half2*)&Ch[(size_t)row * ldc + col] =
                        __floats2half2_rn(v0, v1);
                } else if (MODE == 2) {
                    __half* Ch = (__half*)Cv + (size_t)b * sC;
                    v0 -= uu * g_v[b][col];
                    v1 -= uu * g_v[b][col + 1];
                    *(__half2*)&Ch[(size_t)row * ldc + col] =
                        __floats2half2_rn(v0, v1);
                } else {
                    float* Cf = (float*)Cv + (size_t)b * sC;
                    const float* Eb = E + (size_t)b * sC;
                    const size_t idx = (size_t)row * ldc + col;
                    if (col < NCOL) Cf[idx] = Eb[idx] + v0 * INV_N;
                    if (col + 1 < NCOL) Cf[idx + 1] = Eb[idx + 1] + v1 * INV_N;
                }
            }
        }
    }
}

// ---------------------------------------------------------------------------
// fused setup: z<16 padH(batch z) -> Hp/Ht; z==16 padPQ; z==17 uv.
// grid (34, 12, 18), block 256.
// ---------------------------------------------------------------------------
__global__ void k_setup(const float* __restrict__ H, const float* __restrict__ P,
                        const float* __restrict__ Q) {
    __shared__ float t[32][65];
    const int tid = threadIdx.x;
    const int z = blockIdx.z;

    if (z < NBAT) {
        const int b = z;
        const int c0 = blockIdx.x * 64;
        const int r0 = blockIdx.y * 32;
        const float* Hb = H + (size_t)b * HB;
        const int tx = tid & 31, ty = tid >> 5;
#pragma unroll
        for (int i = 0; i < 4; i++) {
            const int r = r0 + ty + i * 8;
            const int c = c0 + 2 * tx;
            float v0 = 0.0f, v1 = 0.0f;
            if (r < RDIM) {
                if (c < NCOL) v0 = Hb[(size_t)r * NCOL + c];
                if (c + 1 < NCOL) v1 = Hb[(size_t)r * NCOL + c + 1];
            }
            t[ty + i * 8][2 * tx] = v0;
            t[ty + i * 8][2 * tx + 1] = v1;
            *(__half2*)&g_Hp[b][(size_t)r * KHP + c] = __floats2half2_rn(v0, v1);
        }
        __syncthreads();
#pragma unroll
        for (int i = 0; i < 4; i++) {
            const int cl = tid >> 2;
            const int pr = (tid & 3) + 4 * i;
            const float v0 = t[2 * pr][cl];
            const float v1 = t[2 * pr + 1][cl];
            *(__half2*)&g_Ht[b][(size_t)(c0 + cl) * MP + r0 + 2 * pr] =
                __floats2half2_rn(v0, v1);
        }
    } else if (z == NBAT) {
        if (blockIdx.x >= 12) return;
        const int c0 = blockIdx.x * 32, r0 = blockIdx.y * 32;
        const int tx = tid & 31, ty = tid >> 5;
#pragma unroll
        for (int i = 0; i < 4; i++) {
            const int r = r0 + ty + i * 8, c = c0 + tx;
            const bool in = (r < RDIM && c < RDIM);
            g_Pp[(size_t)r * LDS_ + c] =
                __float2half_rn(in ? P[(size_t)r * RDIM + c] : 0.0f);
            t[ty + i * 8][tx] = in ? Q[(size_t)r * RDIM + c] : 0.0f;
        }
        __syncthreads();
#pragma unroll
        for (int i = 0; i < 4; i++) {
            const int c = c0 + ty + i * 8, r = r0 + tx;
            g_Qt[(size_t)c * LDS_ + r] = __float2half_rn(t[tx][ty + i * 8]);
        }
    } else {
        if (blockIdx.x >= NBAT || blockIdx.y != 0) return;
        const int b = blockIdx.x;
        const float* Hb = H + (size_t)b * HB;
        __shared__ float hn[RDIM];
        for (int e = tid; e < RDIM; e += 256)
            hn[e] = Hb[(size_t)e * NCOL + (NCOL - 1)];
        __syncthreads();
        for (int i = tid; i < RDIM; i += 256) {
            float su = 0.0f, sv = 0.0f;
            for (int e = 0; e < RDIM; e++) {
                su += P[(size_t)i * RDIM + e] * hn[e];
                sv += hn[e] * Q[(size_t)e * RDIM + i];
            }
            g_u[b][i] = su;
            g_v[b][i] = sv;
        }
    }
}

// ---------------------------------------------------------------------------
extern "C" void kernel_launch(void* const* d_in, const int* in_sizes, int n_in,
                              void* d_out, int out_size) {
    const float* H = (const float*)d_in[0];
    const float* P = (const float*)d_in[1];
    const float* Q = (const float*)d_in[2];
    float* out = (float*)d_out;

    cudaFuncSetAttribute(k_syrk, cudaFuncAttributeMaxDynamicSharedMemorySize,
                         SMEM_GEMM);
    cudaFuncSetAttribute(k_ld<1>, cudaFuncAttributeMaxDynamicSharedMemorySize,
                         SMEM_GEMM);
    cudaFuncSetAttribute(k_ld<2>, cudaFuncAttributeMaxDynamicSharedMemorySize,
                         SMEM_GEMM);
    cudaFuncSetAttribute(k_ld<3>, cudaFuncAttributeMaxDynamicSharedMemorySize,
                         SMEM_GEMM);

    __half *Pp, *Qt, *Gm, *Tm, *Wm, *Ht;
    cudaGetSymbolAddress((void**)&Pp, g_Pp);
    cudaGetSymbolAddress((void**)&Qt, g_Qt);
    cudaGetSymbolAddress((void**)&Gm, g_G);
    cudaGetSymbolAddress((void**)&Tm, g_Tt);
    cudaGetSymbolAddress((void**)&Wm, g_W);
    cudaGetSymbolAddress((void**)&Ht, g_Ht);

    // 1) setup
    k_setup<<<dim3(34, 12, NBAT + 2), 256>>>(H, P, Q);
    // 2) G partials (symmetric, split-K x3, ldmatrix)
    k_syrk<<<dim3(6, 1, NBAT * 3), 256, SMEM_GEMM>>>();
    // 3) G = sum partials -> fp16
    k_reduce<<<(int)(NBAT * GB_ / 1024), 256>>>();
    // 4) T' = Qt (x) G
    k_ld<1><<<dim3(3, 3, NBAT), 256, SMEM_GEMM>>>(
        Qt, 0, LDS_, Gm, GB_, LDS_, Tm, GB_, LDS_, nullptr);
    // 5) W = Pp (x) T' - u v^T
    k_ld<2><<<dim3(3, 3, NBAT), 256, SMEM_GEMM>>>(
        Pp, 0, LDS_, Tm, GB_, LDS_, Wm, GB_, LDS_, nullptr);
    // 6) out = H + (W (x) Ht)/n
    k_ld<3><<<dim3(17, 3, NBAT), 256, SMEM_GEMM>>>(
        Wm, GB_, LDS_, Ht, (size_t)KHP * MP, MP, out, HB, NCOL, H);
}